// round 4
// baseline (speedup 1.0000x reference)
#include <cuda_runtime.h>
#include <cuda_fp16.h>
#include <math.h>

#define NN 100000
#define NE 3200000
#define EK_BLOCKS 3125
#define EK_ITER   8     // 3125 blocks * 8 warps * 16 edges * 8 iters = 3.2M

// Scratch (device globals; zero-init at load; every invocation restores zeros
// => deterministic under graph replay)
__device__ float    g_deg[NN];
__device__ double   g_sum;
__device__ unsigned g_done;
__device__ __align__(16) __half g_ynorm[NN * 16];   // y * rsqrt(degree), 32B/row
__device__ __align__(16) int2   g_rc[NE];           // packed (row, col) int32

// Per-warp dtype detect: int64 < 100000 => odd 32-bit words all zero.
__device__ __forceinline__ int detect_is64(const void* ei) {
    int lane = threadIdx.x & 31;
    unsigned v = ((const unsigned*)ei)[2 * lane + 1];
    return __ballot_sync(0xffffffffu, v == 0u) == 0xffffffffu;
}

// ---------------------------------------------------------------------------
// Kernel 1: degree = segment_sum(w, row)  AND  pack (row,col) -> g_rc int32.
// ---------------------------------------------------------------------------
__global__ void degree_kernel(const void* __restrict__ ei,
                              const float4* __restrict__ w4) {
    int is64 = detect_is64(ei);
    int t = blockIdx.x * blockDim.x + threadIdx.x;   // grid = NE/4 threads
    float4 w = w4[t];
    int r0, r1, r2, r3, c0, c1, c2, c3;
    if (is64) {
        const longlong2* p = (const longlong2*)ei;            // rows
        const longlong2* q = p + (NE / 2);                    // cols
        longlong2 a = p[2 * t], b = p[2 * t + 1];
        longlong2 e = q[2 * t], f = q[2 * t + 1];
        r0 = (int)a.x; r1 = (int)a.y; r2 = (int)b.x; r3 = (int)b.y;
        c0 = (int)e.x; c1 = (int)e.y; c2 = (int)f.x; c3 = (int)f.y;
    } else {
        const int4* p = (const int4*)ei;
        int4 a = p[t], b = p[NE / 4 + t];
        r0 = a.x; r1 = a.y; r2 = a.z; r3 = a.w;
        c0 = b.x; c1 = b.y; c2 = b.z; c3 = b.w;
    }
    int4* rc4 = (int4*)g_rc;
    rc4[2 * t]     = make_int4(r0, c0, r1, c1);
    rc4[2 * t + 1] = make_int4(r2, c2, r3, c3);
    atomicAdd(&g_deg[r0], w.x);
    atomicAdd(&g_deg[r1], w.y);
    atomicAdd(&g_deg[r2], w.z);
    atomicAdd(&g_deg[r3], w.w);
}

// ---------------------------------------------------------------------------
// Kernel 2: ynorm[n] = y[n] * rsqrt(degree[n]) in fp16; re-zero g_deg.
// ---------------------------------------------------------------------------
__global__ void ynorm_kernel(const float4* __restrict__ y) {
    int i = blockIdx.x * blockDim.x + threadIdx.x;
    if (i >= NN) return;
    float dinv = rsqrtf(g_deg[i]);
    g_deg[i] = 0.0f;                                  // restore invariant
    __half2* out = (__half2*)(g_ynorm + (size_t)i * 16);
    #pragma unroll
    for (int k = 0; k < 4; k++) {
        float4 v = y[i * 4 + k];
        out[2 * k]     = __floats2half2_rn(v.x * dinv, v.y * dinv);
        out[2 * k + 1] = __floats2half2_rn(v.z * dinv, v.w * dinv);
    }
}

// ---------------------------------------------------------------------------
// Kernel 3: per-edge weighted L2 of ynorm[r]-ynorm[c] -> scalar mean in d_out.
// 2 lanes per edge (16B each of the 32B row). One int2 broadcast load per
// edge for indices. Last block writes the mean and restores invariants.
// ---------------------------------------------------------------------------
__global__ void __launch_bounds__(256)
edge_kernel(const float* __restrict__ w, float* __restrict__ out) {
    int tid    = blockIdx.x * blockDim.x + threadIdx.x;
    int warpId = tid >> 5;
    int lane   = threadIdx.x & 31;
    int gid    = lane >> 1;      // edge slot within the warp's 16
    int sub    = lane & 1;       // which 16B half of the 32B row
    int base   = warpId * (16 * EK_ITER);
    const uint4* yn = (const uint4*)g_ynorm;

    // Phase 1: indices + weights (coalesced / broadcast)
    int r[EK_ITER], c[EK_ITER];
    float wv[EK_ITER];
    #pragma unroll
    for (int j = 0; j < EK_ITER; j++) {
        int e = base + j * 16 + gid;
        int2 rc = g_rc[e];
        r[j] = rc.x; c[j] = rc.y;
        wv[j] = w[e];
    }

    // Phase 2: all 16 gathers in flight
    uint4 hr[EK_ITER], hc[EK_ITER];
    #pragma unroll
    for (int j = 0; j < EK_ITER; j++) {
        hr[j] = yn[r[j] * 2 + sub];
        hc[j] = yn[c[j] * 2 + sub];
    }

    // Phase 3: compute
    float acc = 0.0f;
    #pragma unroll
    for (int j = 0; j < EK_ITER; j++) {
        float s = 0.0f;
        const __half2* a2 = (const __half2*)&hr[j];
        const __half2* b2 = (const __half2*)&hc[j];
        #pragma unroll
        for (int k = 0; k < 4; k++) {
            float2 a = __half22float2(a2[k]);
            float2 b = __half22float2(b2[k]);
            float d0 = a.x - b.x;
            float d1 = a.y - b.y;
            s += d0 * d0 + d1 * d1;
        }
        s += __shfl_xor_sync(0xffffffffu, s, 1);
        if (sub == 0) acc += sqrtf(s) * wv[j];
    }

    // Block reduction
    #pragma unroll
    for (int off = 16; off; off >>= 1)
        acc += __shfl_down_sync(0xffffffffu, acc, off);
    __shared__ float warp_sums[8];
    int wid = threadIdx.x >> 5;
    if (lane == 0) warp_sums[wid] = acc;
    __syncthreads();
    if (wid == 0) {
        float v = (lane < 8) ? warp_sums[lane] : 0.0f;
        #pragma unroll
        for (int off = 4; off; off >>= 1)
            v += __shfl_down_sync(0xffffffffu, v, off);
        if (lane == 0) {
            atomicAdd(&g_sum, (double)v);
            __threadfence();
            unsigned ticket = atomicAdd(&g_done, 1u);
            if (ticket == EK_BLOCKS - 1) {            // last block: finalize
                out[0] = (float)(g_sum / (double)NE);
                g_sum  = 0.0;                          // restore invariants
                g_done = 0u;
                __threadfence();
            }
        }
    }
}

extern "C" void kernel_launch(void* const* d_in, const int* in_sizes, int n_in,
                              void* d_out, int out_size) {
    const void*  ei = d_in[0];                  // edge_index (2, NE)
    const float* w  = (const float*)d_in[1];    // edge_weights (NE,)
    const float* y  = (const float*)d_in[2];    // y (NN, 16)

    degree_kernel<<<NE / 4 / 256, 256>>>(ei, (const float4*)w);
    ynorm_kernel<<<(NN + 255) / 256, 256>>>((const float4*)y);
    edge_kernel<<<EK_BLOCKS, 256>>>(w, (float*)d_out);
}